// round 4
// baseline (speedup 1.0000x reference)
#include <cuda_runtime.h>

// Problem constants
#define BT    8192          // B*T rows
#define CDIM  1024

// ---------------------------------------------------------------------------
// Scratch (no cudaMalloc allowed -> __device__ globals)
// ---------------------------------------------------------------------------
__device__ float g_ln [BT * CDIM];          //  32 MB
__device__ float g_qkv[BT * 3 * CDIM];      //  96 MB
__device__ float g_att[BT * CDIM];          //  32 MB
__device__ float g_x1 [BT * CDIM];          //  32 MB
__device__ float g_h  [BT * 4 * CDIM];      // 128 MB

// ---------------------------------------------------------------------------
// Packed fp32x2 helpers (Blackwell: doubles fp32 FMA throughput vs FFMA-3reg)
// ---------------------------------------------------------------------------
__device__ __forceinline__ void ffma2(unsigned long long &d,
                                      unsigned long long a,
                                      unsigned long long b) {
    asm("fma.rn.f32x2 %0, %1, %2, %0;" : "+l"(d) : "l"(a), "l"(b));
}
__device__ __forceinline__ unsigned long long dup2(float a) {
    unsigned long long r;
    asm("mov.b64 %0, {%1, %1};" : "=l"(r) : "f"(a));
    return r;
}
__device__ __forceinline__ float2 unpk(unsigned long long v) {
    float2 r;
    asm("mov.b64 {%0, %1}, %2;" : "=f"(r.x), "=f"(r.y) : "l"(v));
    return r;
}

__device__ __forceinline__ float gelu_tanh(float x) {
    float u = 0.7978845608028654f * (x + 0.044715f * x * x * x);
    return 0.5f * x * (1.0f + tanhf(u));
}

// ---------------------------------------------------------------------------
// LayerNorm: one block per row of 1024, 256 threads, 1 float4 per thread
// ---------------------------------------------------------------------------
__global__ __launch_bounds__(256)
void ln_kernel(const float* __restrict__ x, const float* __restrict__ w,
               const float* __restrict__ bb, float* __restrict__ out) {
    int row = blockIdx.x;
    int t = threadIdx.x;
    const float4 v = reinterpret_cast<const float4*>(x)[row * 256 + t];
    float s = v.x + v.y + v.z + v.w;
    float q = v.x*v.x + v.y*v.y + v.z*v.z + v.w*v.w;
#pragma unroll
    for (int off = 16; off; off >>= 1) {
        s += __shfl_xor_sync(0xffffffffu, s, off);
        q += __shfl_xor_sync(0xffffffffu, q, off);
    }
    __shared__ float sh_s[8], sh_q[8];
    __shared__ float sh_mean, sh_rstd;
    int wid = t >> 5;
    if ((t & 31) == 0) { sh_s[wid] = s; sh_q[wid] = q; }
    __syncthreads();
    if (t == 0) {
        float ts = 0.f, tq = 0.f;
#pragma unroll
        for (int i = 0; i < 8; i++) { ts += sh_s[i]; tq += sh_q[i]; }
        float mean = ts * (1.0f / 1024.0f);
        float var  = tq * (1.0f / 1024.0f) - mean * mean;
        sh_mean = mean;
        sh_rstd = rsqrtf(var + 1e-5f);
    }
    __syncthreads();
    float mean = sh_mean, rstd = sh_rstd;
    const float4 wv = reinterpret_cast<const float4*>(w)[t];
    const float4 bv = reinterpret_cast<const float4*>(bb)[t];
    float4 o;
    o.x = (v.x - mean) * rstd * wv.x + bv.x;
    o.y = (v.y - mean) * rstd * wv.y + bv.y;
    o.z = (v.z - mean) * rstd * wv.z + bv.z;
    o.w = (v.w - mean) * rstd * wv.w + bv.w;
    reinterpret_cast<float4*>(out)[row * 256 + t] = o;
}

// ---------------------------------------------------------------------------
// GEMM: C[M,N] = A[M,K] @ B[K,N] + bias (+res) (gelu)
// 128x128 block tile, BK=8, 256 threads, 8x8 per thread via fp32x2 FFMA2.
// EPI: 0 = +bias, 1 = +bias+residual, 2 = gelu(+bias)
// ---------------------------------------------------------------------------
template<int EPI>
__global__ __launch_bounds__(256, 2)
void gemm_kernel(const float* __restrict__ A, const float* __restrict__ B,
                 const float* __restrict__ bias, const float* __restrict__ res,
                 float* __restrict__ C, int M, int N, int K) {
    __shared__ float As[8][128];   // transposed: As[k][m]
    __shared__ float Bs[8][128];   // Bs[k][n]

    int tid = threadIdx.x;
    int bm = blockIdx.y * 128, bn = blockIdx.x * 128;

    int arow = tid >> 1, acol = (tid & 1) * 4;    // A tile: 128 rows x 8 cols
    int brow = tid >> 5, bcol = (tid & 31) * 4;   // B tile: 8 rows x 128 cols
    const float* Ap = A + (bm + arow) * K + acol;
    const float* Bp = B + brow * N + bn + bcol;

    float4 ar = *reinterpret_cast<const float4*>(Ap);
    float4 br = *reinterpret_cast<const float4*>(Bp);

    unsigned long long acc[8][4];
#pragma unroll
    for (int i = 0; i < 8; i++)
#pragma unroll
        for (int j = 0; j < 4; j++) acc[i][j] = 0ull;

    int ty = tid >> 4, tx = tid & 15;

    for (int kt = 0; kt < K; kt += 8) {
        As[acol + 0][arow] = ar.x;
        As[acol + 1][arow] = ar.y;
        As[acol + 2][arow] = ar.z;
        As[acol + 3][arow] = ar.w;
        *reinterpret_cast<float4*>(&Bs[brow][bcol]) = br;
        __syncthreads();
        if (kt + 8 < K) {   // register prefetch of next tile
            ar = *reinterpret_cast<const float4*>(Ap + kt + 8);
            br = *reinterpret_cast<const float4*>(Bp + (kt + 8) * N);
        }
#pragma unroll
        for (int kk = 0; kk < 8; kk++) {
            float4 a0 = *reinterpret_cast<const float4*>(&As[kk][ty * 4]);
            float4 a1 = *reinterpret_cast<const float4*>(&As[kk][64 + ty * 4]);
            unsigned long long b0 = *reinterpret_cast<const unsigned long long*>(&Bs[kk][tx * 4]);
            unsigned long long b1 = *reinterpret_cast<const unsigned long long*>(&Bs[kk][tx * 4 + 2]);
            unsigned long long b2 = *reinterpret_cast<const unsigned long long*>(&Bs[kk][64 + tx * 4]);
            unsigned long long b3 = *reinterpret_cast<const unsigned long long*>(&Bs[kk][64 + tx * 4 + 2]);
            float av[8] = {a0.x, a0.y, a0.z, a0.w, a1.x, a1.y, a1.z, a1.w};
#pragma unroll
            for (int i = 0; i < 8; i++) {
                unsigned long long ad = dup2(av[i]);
                ffma2(acc[i][0], ad, b0);
                ffma2(acc[i][1], ad, b1);
                ffma2(acc[i][2], ad, b2);
                ffma2(acc[i][3], ad, b3);
            }
        }
        __syncthreads();
    }

    // Epilogue
#pragma unroll
    for (int ih = 0; ih < 2; ih++)
#pragma unroll
    for (int i = 0; i < 4; i++) {
        int r = bm + ih * 64 + ty * 4 + i;
#pragma unroll
        for (int jh = 0; jh < 2; jh++) {
            int c = bn + jh * 64 + tx * 4;
            float2 p0 = unpk(acc[ih * 4 + i][jh * 2 + 0]);
            float2 p1 = unpk(acc[ih * 4 + i][jh * 2 + 1]);
            float4 bbv = *reinterpret_cast<const float4*>(&bias[c]);
            float4 v;
            v.x = p0.x + bbv.x; v.y = p0.y + bbv.y;
            v.z = p1.x + bbv.z; v.w = p1.y + bbv.w;
            if (EPI == 1) {
                float4 rv = *reinterpret_cast<const float4*>(&res[r * N + c]);
                v.x += rv.x; v.y += rv.y; v.z += rv.z; v.w += rv.w;
            }
            if (EPI == 2) {
                v.x = gelu_tanh(v.x); v.y = gelu_tanh(v.y);
                v.z = gelu_tanh(v.z); v.w = gelu_tanh(v.w);
            }
            *reinterpret_cast<float4*>(&C[r * N + c]) = v;
        }
    }
}

// ---------------------------------------------------------------------------
// Causal flash attention. Grid (qtile=16, h=16, b=8), 256 threads.
// 64x64 Q/K tiles, D=64, online softmax. Q pre-scaled by 1/sqrt(D)=0.125.
// Dynamic smem: 4 * 64*65 floats = 66,560 B.
// ---------------------------------------------------------------------------
#define AT_PAD 65
#define ATT_SMEM (4 * 64 * AT_PAD * (int)sizeof(float))

__global__ __launch_bounds__(256)
void attn_kernel(const float* __restrict__ qkv, float* __restrict__ y) {
    extern __shared__ float sm[];
    float* Qs = sm;                    // [64][65]  (q, d)
    float* Ks = sm + 64 * AT_PAD;      // [64][65]  (k, d)
    float* Vs = sm + 2 * 64 * AT_PAD;  // [64][65]  (k, d)
    float* Ps = sm + 3 * 64 * AT_PAD;  // [64][65]  (q, k)

    int qt = blockIdx.x, h = blockIdx.y, b = blockIdx.z;
    int tid = threadIdx.x;
    int tx = tid & 15, ty = tid >> 4;
    int qrow0 = ty * 4, kcol0 = tx * 4;

    const float* qbase = qkv + (size_t)(b * 1024 + qt * 64) * 3072 + h * 64;
#pragma unroll
    for (int it = 0; it < 4; it++) {
        int idx = it * 1024 + tid * 4;
        int qq = idx >> 6, d = idx & 63;
        float4 v = *reinterpret_cast<const float4*>(qbase + (size_t)qq * 3072 + d);
        float* p = Qs + qq * AT_PAD + d;
        p[0] = v.x * 0.125f; p[1] = v.y * 0.125f;
        p[2] = v.z * 0.125f; p[3] = v.w * 0.125f;
    }

    const float NEG_INF = __int_as_float(0xff800000);
    float m[4], l[4], o[4][4];
#pragma unroll
    for (int i = 0; i < 4; i++) {
        m[i] = NEG_INF; l[i] = 0.f;
#pragma unroll
        for (int jj = 0; jj < 4; jj++) o[i][jj] = 0.f;
    }

    for (int j = 0; j <= qt; j++) {
        __syncthreads();  // previous PV done; Q store visible (1st iter)
        const float* kbase = qkv + (size_t)(b * 1024 + j * 64) * 3072 + 1024 + h * 64;
#pragma unroll
        for (int it = 0; it < 4; it++) {
            int idx = it * 1024 + tid * 4;
            int kk = idx >> 6, d = idx & 63;
            float4 kv = *reinterpret_cast<const float4*>(kbase + (size_t)kk * 3072 + d);
            float4 vv = *reinterpret_cast<const float4*>(kbase + (size_t)kk * 3072 + 1024 + d);
            float* kp = Ks + kk * AT_PAD + d;
            float* vp = Vs + kk * AT_PAD + d;
            kp[0] = kv.x; kp[1] = kv.y; kp[2] = kv.z; kp[3] = kv.w;
            vp[0] = vv.x; vp[1] = vv.y; vp[2] = vv.z; vp[3] = vv.w;
        }
        __syncthreads();

        // S = Q @ K^T (scaled)
        float s[4][4];
#pragma unroll
        for (int i = 0; i < 4; i++)
#pragma unroll
            for (int jj = 0; jj < 4; jj++) s[i][jj] = 0.f;
        const float* q0 = Qs + (qrow0 + 0) * AT_PAD;
        const float* q1 = Qs + (qrow0 + 1) * AT_PAD;
        const float* q2 = Qs + (qrow0 + 2) * AT_PAD;
        const float* q3 = Qs + (qrow0 + 3) * AT_PAD;
        const float* k0 = Ks + (kcol0 + 0) * AT_PAD;
        const float* k1 = Ks + (kcol0 + 1) * AT_PAD;
        const float* k2 = Ks + (kcol0 + 2) * AT_PAD;
        const float* k3 = Ks + (kcol0 + 3) * AT_PAD;
#pragma unroll 8
        for (int d = 0; d < 64; d++) {
            float qv0 = q0[d], qv1 = q1[d], qv2 = q2[d], qv3 = q3[d];
            float kv0 = k0[d], kv1 = k1[d], kv2 = k2[d], kv3 = k3[d];
            s[0][0] += qv0 * kv0; s[0][1] += qv0 * kv1; s[0][2] += qv0 * kv2; s[0][3] += qv0 * kv3;
            s[1][0] += qv1 * kv0; s[1][1] += qv1 * kv1; s[1][2] += qv1 * kv2; s[1][3] += qv1 * kv3;
            s[2][0] += qv2 * kv0; s[2][1] += qv2 * kv1; s[2][2] += qv2 * kv2; s[2][3] += qv2 * kv3;
            s[3][0] += qv3 * kv0; s[3][1] += qv3 * kv1; s[3][2] += qv3 * kv2; s[3][3] += qv3 * kv3;
        }
        if (j == qt) {  // causal mask only needed on the diagonal tile
#pragma unroll
            for (int i = 0; i < 4; i++)
#pragma unroll
                for (int jj = 0; jj < 4; jj++)
                    if (kcol0 + jj > qrow0 + i) s[i][jj] = NEG_INF;
        }

        // Online softmax (rows split across 16 lanes with same ty)
#pragma unroll
        for (int i = 0; i < 4; i++) {
            float rm = fmaxf(fmaxf(s[i][0], s[i][1]), fmaxf(s[i][2], s[i][3]));
#pragma unroll
            for (int off = 8; off; off >>= 1)
                rm = fmaxf(rm, __shfl_xor_sync(0xffffffffu, rm, off, 16));
            float mn = fmaxf(m[i], rm);
            float sc = __expf(m[i] - mn);
            float rs = 0.f;
#pragma unroll
            for (int jj = 0; jj < 4; jj++) {
                float p = __expf(s[i][jj] - mn);
                s[i][jj] = p; rs += p;
            }
#pragma unroll
            for (int off = 8; off; off >>= 1)
                rs += __shfl_xor_sync(0xffffffffu, rs, off, 16);
            l[i] = l[i] * sc + rs;
            o[i][0] *= sc; o[i][1] *= sc; o[i][2] *= sc; o[i][3] *= sc;
            m[i] = mn;
            float* pp = Ps + (qrow0 + i) * AT_PAD + kcol0;
            pp[0] = s[i][0]; pp[1] = s[i][1]; pp[2] = s[i][2]; pp[3] = s[i][3];
        }
        __syncthreads();  // Ps ready

        // O += P @ V
        const float* P0 = Ps + (qrow0 + 0) * AT_PAD;
        const float* P1 = Ps + (qrow0 + 1) * AT_PAD;
        const float* P2 = Ps + (qrow0 + 2) * AT_PAD;
        const float* P3 = Ps + (qrow0 + 3) * AT_PAD;
#pragma unroll 8
        for (int kk = 0; kk < 64; kk++) {
            float p0 = P0[kk], p1 = P1[kk], p2 = P2[kk], p3 = P3[kk];
            const float* vr = Vs + kk * AT_PAD + kcol0;
            float v0 = vr[0], v1 = vr[1], v2 = vr[2], v3 = vr[3];
            o[0][0] += p0 * v0; o[0][1] += p0 * v1; o[0][2] += p0 * v2; o[0][3] += p0 * v3;
            o[1][0] += p1 * v0; o[1][1] += p1 * v1; o[1][2] += p1 * v2; o[1][3] += p1 * v3;
            o[2][0] += p2 * v0; o[2][1] += p2 * v1; o[2][2] += p2 * v2; o[2][3] += p2 * v3;
            o[3][0] += p3 * v0; o[3][1] += p3 * v1; o[3][2] += p3 * v2; o[3][3] += p3 * v3;
        }
    }

    float* ybase = y + (size_t)(b * 1024 + qt * 64) * 1024 + h * 64;
#pragma unroll
    for (int i = 0; i < 4; i++) {
        float inv = 1.0f / l[i];
        float4 v = make_float4(o[i][0] * inv, o[i][1] * inv,
                               o[i][2] * inv, o[i][3] * inv);
        *reinterpret_cast<float4*>(ybase + (size_t)(qrow0 + i) * 1024 + kcol0) = v;
    }
}

// ---------------------------------------------------------------------------
// Launch pipeline (graph-capturable: kernel launches only)
// ---------------------------------------------------------------------------
extern "C" void kernel_launch(void* const* d_in, const int* in_sizes, int n_in,
                              void* d_out, int out_size) {
    const float* x      = (const float*)d_in[0];
    const float* ln1_w  = (const float*)d_in[1];
    const float* ln1_b  = (const float*)d_in[2];
    const float* w_qkv  = (const float*)d_in[3];
    const float* b_qkv  = (const float*)d_in[4];
    const float* w_o    = (const float*)d_in[5];
    const float* b_o    = (const float*)d_in[6];
    const float* ln2_w  = (const float*)d_in[7];
    const float* ln2_b  = (const float*)d_in[8];
    const float* w_fc   = (const float*)d_in[9];
    const float* b_fc   = (const float*)d_in[10];
    const float* w_proj = (const float*)d_in[11];
    const float* b_proj = (const float*)d_in[12];
    float* out = (float*)d_out;

    float *p_ln, *p_qkv, *p_att, *p_x1, *p_h;
    cudaGetSymbolAddress((void**)&p_ln,  g_ln);
    cudaGetSymbolAddress((void**)&p_qkv, g_qkv);
    cudaGetSymbolAddress((void**)&p_att, g_att);
    cudaGetSymbolAddress((void**)&p_x1,  g_x1);
    cudaGetSymbolAddress((void**)&p_h,   g_h);

    cudaFuncSetAttribute(attn_kernel,
                         cudaFuncAttributeMaxDynamicSharedMemorySize, ATT_SMEM);

    // 1) LN1
    ln_kernel<<<BT, 256>>>(x, ln1_w, ln1_b, p_ln);
    // 2) QKV = ln1 @ w_qkv + b_qkv          [8192,3072]
    gemm_kernel<0><<<dim3(24, 64), 256>>>(p_ln, w_qkv, b_qkv, nullptr, p_qkv,
                                          BT, 3 * CDIM, CDIM);
    // 3) causal attention -> y              [8192,1024]
    attn_kernel<<<dim3(16, 16, 8), 256, ATT_SMEM>>>(p_qkv, p_att);
    // 4) x1 = y @ w_o + b_o + x             [8192,1024]
    gemm_kernel<1><<<dim3(8, 64), 256>>>(p_att, w_o, b_o, x, p_x1,
                                         BT, CDIM, CDIM);
    // 5) LN2
    ln_kernel<<<BT, 256>>>(p_x1, ln2_w, ln2_b, p_ln);
    // 6) h = gelu(ln2 @ w_fc + b_fc)        [8192,4096]
    gemm_kernel<2><<<dim3(32, 64), 256>>>(p_ln, w_fc, b_fc, nullptr, p_h,
                                          BT, 4 * CDIM, CDIM);
    // 7) out = h @ w_proj + b_proj + x1     [8192,1024]
    gemm_kernel<1><<<dim3(8, 64), 256>>>(p_h, w_proj, b_proj, p_x1, out,
                                         BT, CDIM, 4 * CDIM);
}

// round 10
// speedup vs baseline: 1.8747x; 1.8747x over previous
#include <cuda_runtime.h>
#include <cuda_bf16.h>
#include <cstdint>

#define BT    8192
#define CDIM  1024

// ---------------------------------------------------------------------------
// Scratch (__device__ globals; no cudaMalloc allowed)
// ---------------------------------------------------------------------------
__device__ __align__(256) __nv_bfloat16 g_lnh[BT * CDIM];
__device__ __align__(256) __nv_bfloat16 g_lnl[BT * CDIM];
__device__ __align__(256) float         g_qkv[BT * 3 * CDIM];
__device__ __align__(256) __nv_bfloat16 g_atth[BT * CDIM];
__device__ __align__(256) __nv_bfloat16 g_attl[BT * CDIM];
__device__ __align__(256) float         g_x1[BT * CDIM];
__device__ __align__(256) __nv_bfloat16 g_hh[BT * 4 * CDIM];
__device__ __align__(256) __nv_bfloat16 g_hl[BT * 4 * CDIM];
// transposed split weights: [N, K] row-major bf16
__device__ __align__(256) __nv_bfloat16 g_wqkvh[3 * CDIM * CDIM];
__device__ __align__(256) __nv_bfloat16 g_wqkvl[3 * CDIM * CDIM];
__device__ __align__(256) __nv_bfloat16 g_woh[CDIM * CDIM];
__device__ __align__(256) __nv_bfloat16 g_wol[CDIM * CDIM];
__device__ __align__(256) __nv_bfloat16 g_wfch[4 * CDIM * CDIM];
__device__ __align__(256) __nv_bfloat16 g_wfcl[4 * CDIM * CDIM];
__device__ __align__(256) __nv_bfloat16 g_wprojh[CDIM * 4 * CDIM];
__device__ __align__(256) __nv_bfloat16 g_wprojl[CDIM * 4 * CDIM];

// ---------------------------------------------------------------------------
// PTX helpers (sm_80-baseline only: cp.async, ldmatrix, mma.sync)
// ---------------------------------------------------------------------------
__device__ __forceinline__ uint32_t smem_u32(const void* p) {
    uint32_t a;
    asm("{ .reg .u64 t; cvta.to.shared.u64 t, %1; cvt.u32.u64 %0, t; }"
        : "=r"(a) : "l"(p));
    return a;
}
__device__ __forceinline__ void cpa16(uint32_t s, const void* g) {
    asm volatile("cp.async.cg.shared.global [%0], [%1], 16;" :: "r"(s), "l"(g));
}
#define CP_COMMIT()  asm volatile("cp.async.commit_group;" ::: "memory")
#define CP_WAIT1()   asm volatile("cp.async.wait_group 1;" ::: "memory")
#define CP_WAIT0()   asm volatile("cp.async.wait_group 0;" ::: "memory")

__device__ __forceinline__ void ldsm_x4(uint32_t* r, uint32_t addr) {
    asm volatile("ldmatrix.sync.aligned.m8n8.x4.shared.b16 {%0,%1,%2,%3}, [%4];"
                 : "=r"(r[0]), "=r"(r[1]), "=r"(r[2]), "=r"(r[3]) : "r"(addr));
}
// D(f32) += A(bf16,row) * B(bf16,col) : m16n8k16.  b0 = k0-7, b1 = k8-15.
__device__ __forceinline__ void mma16816(float* d, const uint32_t* a,
                                         uint32_t b0, uint32_t b1) {
    asm volatile(
        "mma.sync.aligned.m16n8k16.row.col.f32.bf16.bf16.f32 "
        "{%0,%1,%2,%3}, {%4,%5,%6,%7}, {%8,%9}, {%0,%1,%2,%3};"
        : "+f"(d[0]), "+f"(d[1]), "+f"(d[2]), "+f"(d[3])
        : "r"(a[0]), "r"(a[1]), "r"(a[2]), "r"(a[3]), "r"(b0), "r"(b1));
}

#define SWZ(o) ((o) ^ (((o) >> 3) & 0x70))

__device__ __forceinline__ void bsplit(float v, __nv_bfloat16& h, __nv_bfloat16& l) {
    h = __float2bfloat16_rn(v);
    l = __float2bfloat16_rn(v - __bfloat162float(h));
}
__device__ __forceinline__ float gelu_tanh(float x) {
    float u = 0.7978845608028654f * (x + 0.044715f * x * x * x);
    return 0.5f * x * (1.0f + tanhf(u));
}

// ---------------------------------------------------------------------------
// Weight transpose + bf16 hi/lo split:  W[K,N] f32 -> Th/Tl [N,K] bf16
// ---------------------------------------------------------------------------
__global__ __launch_bounds__(256)
void wsplit_kernel(const float* __restrict__ W,
                   __nv_bfloat16* __restrict__ Th, __nv_bfloat16* __restrict__ Tl,
                   int K, int N) {
    __shared__ float t[32][33];
    int n0 = blockIdx.x * 32, k0 = blockIdx.y * 32;
    int tx = threadIdx.x, ty = threadIdx.y;   // 32 x 8
#pragma unroll
    for (int i = 0; i < 4; i++)
        t[ty + 8 * i][tx] = W[(size_t)(k0 + ty + 8 * i) * N + n0 + tx];
    __syncthreads();
#pragma unroll
    for (int i = 0; i < 4; i++) {
        int nn = ty + 8 * i;
        float v = t[tx][nn];                  // = W[k0+tx][n0+nn]
        __nv_bfloat16 h, l;
        bsplit(v, h, l);
        size_t o = (size_t)(n0 + nn) * K + k0 + tx;
        Th[o] = h; Tl[o] = l;
    }
}

// ---------------------------------------------------------------------------
// LayerNorm -> bf16 hi/lo
// ---------------------------------------------------------------------------
__global__ __launch_bounds__(256)
void ln_split_kernel(const float* __restrict__ x, const float* __restrict__ w,
                     const float* __restrict__ bb,
                     __nv_bfloat16* __restrict__ oh, __nv_bfloat16* __restrict__ ol) {
    int row = blockIdx.x;
    int t = threadIdx.x;
    const float4 v = reinterpret_cast<const float4*>(x)[row * 256 + t];
    float s = v.x + v.y + v.z + v.w;
    float q = v.x * v.x + v.y * v.y + v.z * v.z + v.w * v.w;
#pragma unroll
    for (int off = 16; off; off >>= 1) {
        s += __shfl_xor_sync(0xffffffffu, s, off);
        q += __shfl_xor_sync(0xffffffffu, q, off);
    }
    __shared__ float sh_s[8], sh_q[8], sh_mean, sh_rstd;
    int wid = t >> 5;
    if ((t & 31) == 0) { sh_s[wid] = s; sh_q[wid] = q; }
    __syncthreads();
    if (t == 0) {
        float ts = 0.f, tq = 0.f;
#pragma unroll
        for (int i = 0; i < 8; i++) { ts += sh_s[i]; tq += sh_q[i]; }
        float mean = ts * (1.0f / 1024.0f);
        float var  = tq * (1.0f / 1024.0f) - mean * mean;
        sh_mean = mean; sh_rstd = rsqrtf(var + 1e-5f);
    }
    __syncthreads();
    float mean = sh_mean, rstd = sh_rstd;
    const float4 wv = reinterpret_cast<const float4*>(w)[t];
    const float4 bv = reinterpret_cast<const float4*>(bb)[t];
    float o0 = (v.x - mean) * rstd * wv.x + bv.x;
    float o1 = (v.y - mean) * rstd * wv.y + bv.y;
    float o2 = (v.z - mean) * rstd * wv.z + bv.z;
    float o3 = (v.w - mean) * rstd * wv.w + bv.w;
    __nv_bfloat16 h0, l0, h1, l1, h2, l2, h3, l3;
    bsplit(o0, h0, l0); bsplit(o1, h1, l1);
    bsplit(o2, h2, l2); bsplit(o3, h3, l3);
    size_t base = (size_t)row * 1024 + t * 4;
    *reinterpret_cast<__nv_bfloat162*>(oh + base)     = __nv_bfloat162(h0, h1);
    *reinterpret_cast<__nv_bfloat162*>(oh + base + 2) = __nv_bfloat162(h2, h3);
    *reinterpret_cast<__nv_bfloat162*>(ol + base)     = __nv_bfloat162(l0, l1);
    *reinterpret_cast<__nv_bfloat162*>(ol + base + 2) = __nv_bfloat162(l2, l3);
}

// ---------------------------------------------------------------------------
// HMMA GEMM: C[M,N] = (Ah+Al)[M,K] @ (Bh+Bl)^T[N,K] + bias ...
// 3-MMA split: Ah*Bh + Ah*Bl + Al*Bh in f32 accumulators.
// CTA tile 128x128, K-chunk 64, 2-stage cp.async, 8 warps (4m x 2n),
// warp tile 32x64 via m16n8k16 mma.sync.
// EPI: 0 = +bias -> f32; 1 = +bias+res -> f32; 2 = gelu(+bias) -> bf16 hi/lo
// ---------------------------------------------------------------------------
#define STAGE_B 65536                        // Ah|Al|Bh|Bl  4 x 16KB
#define GSMEM   (2 * STAGE_B)                // 128KB dynamic

template<int EPI>
__global__ __launch_bounds__(256, 1)
void gemm_mma(const __nv_bfloat16* __restrict__ Ah, const __nv_bfloat16* __restrict__ Al,
              const __nv_bfloat16* __restrict__ Bh, const __nv_bfloat16* __restrict__ Bl,
              const float* __restrict__ bias, const float* __restrict__ res,
              float* __restrict__ Cf,
              __nv_bfloat16* __restrict__ Ch, __nv_bfloat16* __restrict__ Cl,
              int M, int N, int K) {
    extern __shared__ char smem[];
    const uint32_t sb0 = smem_u32(smem);
    const int tid = threadIdx.x;
    const int wid = tid >> 5, lane = tid & 31;
    const int bm = blockIdx.y * 128, bn = blockIdx.x * 128;
    const int warp_m = (wid & 3) * 32, warp_n = (wid >> 2) * 64;
    const int nchunks = K >> 6;

    // cp.async offsets: tiles are 128 rows x 128 bytes (64 bf16 of K)
    size_t gA[4], gB[4]; uint32_t sT[4];
#pragma unroll
    for (int i = 0; i < 4; i++) {
        int id = tid + i * 256;
        int r = id >> 3, cb = (id & 7) * 16;
        gA[i] = (size_t)(bm + r) * K * 2 + cb;
        gB[i] = (size_t)(bn + r) * K * 2 + cb;
        sT[i] = SWZ(r * 128 + cb);
    }
    const char* pAh = (const char*)Ah; const char* pAl = (const char*)Al;
    const char* pBh = (const char*)Bh; const char* pBl = (const char*)Bl;

    auto issue_loads = [&](int c, int buf) {
        uint32_t sbase = sb0 + buf * STAGE_B;
        size_t cb = (size_t)c * 128;
#pragma unroll
        for (int i = 0; i < 4; i++) {
            cpa16(sbase +         sT[i], pAh + gA[i] + cb);
            cpa16(sbase + 16384 + sT[i], pAl + gA[i] + cb);
            cpa16(sbase + 32768 + sT[i], pBh + gB[i] + cb);
            cpa16(sbase + 49152 + sT[i], pBl + gB[i] + cb);
        }
        CP_COMMIT();
    };

    float acc[2][8][4];
#pragma unroll
    for (int mt = 0; mt < 2; mt++)
#pragma unroll
        for (int nt = 0; nt < 8; nt++)
#pragma unroll
            for (int j = 0; j < 4; j++) acc[mt][nt][j] = 0.f;

    // ldmatrix lane mapping: group g covers (row +8*(g&1), k +8*(g>>1))
    const int g = lane >> 3, lr = lane & 7;
    const int arow = warp_m + (g & 1) * 8 + lr;
    const int brow = warp_n + (g & 1) * 8 + lr;
    const int koffb = (g >> 1) * 16;

    issue_loads(0, 0);

    for (int c = 0; c < nchunks; c++) {
        int buf = c & 1;
        if (c + 1 < nchunks) { issue_loads(c + 1, buf ^ 1); CP_WAIT1(); }
        else                 { CP_WAIT0(); }
        __syncthreads();
        uint32_t base = sb0 + buf * STAGE_B;
#pragma unroll
        for (int ks = 0; ks < 4; ks++) {
            uint32_t ah[2][4], al[2][4];
#pragma unroll
            for (int mt = 0; mt < 2; mt++) {
                uint32_t off = SWZ((arow + mt * 16) * 128 + ks * 32 + koffb);
                ldsm_x4(ah[mt], base + off);
                ldsm_x4(al[mt], base + 16384 + off);
            }
            uint32_t bh[4][4], bl[4][4];
#pragma unroll
            for (int nt2 = 0; nt2 < 4; nt2++) {
                uint32_t off = SWZ((brow + nt2 * 16) * 128 + ks * 32 + koffb);
                ldsm_x4(bh[nt2], base + 32768 + off);
                ldsm_x4(bl[nt2], base + 49152 + off);
            }
            // B frag for n-subblock s of tile t: {reg[s], reg[s+2]} (k-low, k-high)
#pragma unroll
            for (int mt = 0; mt < 2; mt++)
#pragma unroll
                for (int nt = 0; nt < 8; nt++) {
                    int t2 = nt >> 1, s = nt & 1;
                    mma16816(acc[mt][nt], ah[mt], bh[t2][s], bh[t2][s + 2]);
                    mma16816(acc[mt][nt], ah[mt], bl[t2][s], bl[t2][s + 2]);
                    mma16816(acc[mt][nt], al[mt], bh[t2][s], bh[t2][s + 2]);
                }
        }
        __syncthreads();   // protect this buffer before it is refilled
    }

    // Epilogue: D frag: d0,d1 -> (m = lane>>2, n = (lane&3)*2); d2,d3 -> m+8
    const int mrow = lane >> 2, ncol = (lane & 3) * 2;
#pragma unroll
    for (int mt = 0; mt < 2; mt++)
#pragma unroll
        for (int nt = 0; nt < 8; nt++) {
            int n_g = bn + warp_n + nt * 8 + ncol;
            float2 bv = *reinterpret_cast<const float2*>(&bias[n_g]);
#pragma unroll
            for (int half = 0; half < 2; half++) {
                int m_g = bm + warp_m + mt * 16 + mrow + half * 8;
                float vx = acc[mt][nt][half * 2 + 0] + bv.x;
                float vy = acc[mt][nt][half * 2 + 1] + bv.y;
                size_t o = (size_t)m_g * N + n_g;
                if (EPI == 1) {
                    float2 rv = *reinterpret_cast<const float2*>(&res[o]);
                    vx += rv.x; vy += rv.y;
                }
                if (EPI == 2) {
                    float g0 = gelu_tanh(vx), g1 = gelu_tanh(vy);
                    __nv_bfloat16 h0, l0, h1, l1;
                    bsplit(g0, h0, l0); bsplit(g1, h1, l1);
                    *reinterpret_cast<__nv_bfloat162*>(Ch + o) = __nv_bfloat162(h0, h1);
                    *reinterpret_cast<__nv_bfloat162*>(Cl + o) = __nv_bfloat162(l0, l1);
                } else {
                    *reinterpret_cast<float2*>(&Cf[o]) = make_float2(vx, vy);
                }
            }
        }
}

// ---------------------------------------------------------------------------
// Causal flash attention (fp32), writes bf16 hi/lo output.
// Grid (qtile=16, h=16, b=8), 256 threads, 64x64 tiles, D=64.
// ---------------------------------------------------------------------------
#define AT_PAD 65
#define ATT_SMEM (4 * 64 * AT_PAD * (int)sizeof(float))

__global__ __launch_bounds__(256)
void attn_kernel(const float* __restrict__ qkv,
                 __nv_bfloat16* __restrict__ yh, __nv_bfloat16* __restrict__ yl) {
    extern __shared__ float sm[];
    float* Qs = sm;
    float* Ks = sm + 64 * AT_PAD;
    float* Vs = sm + 2 * 64 * AT_PAD;
    float* Ps = sm + 3 * 64 * AT_PAD;

    int qt = blockIdx.x, h = blockIdx.y, b = blockIdx.z;
    int tid = threadIdx.x;
    int tx = tid & 15, ty = tid >> 4;
    int qrow0 = ty * 4, kcol0 = tx * 4;

    const float* qbase = qkv + (size_t)(b * 1024 + qt * 64) * 3072 + h * 64;
#pragma unroll
    for (int it = 0; it < 4; it++) {
        int idx = it * 1024 + tid * 4;
        int qq = idx >> 6, d = idx & 63;
        float4 v = *reinterpret_cast<const float4*>(qbase + (size_t)qq * 3072 + d);
        float* p = Qs + qq * AT_PAD + d;
        p[0] = v.x * 0.125f; p[1] = v.y * 0.125f;
        p[2] = v.z * 0.125f; p[3] = v.w * 0.125f;
    }

    const float NEG_INF = __int_as_float(0xff800000);
    float m[4], l[4], o[4][4];
#pragma unroll
    for (int i = 0; i < 4; i++) {
        m[i] = NEG_INF; l[i] = 0.f;
#pragma unroll
        for (int jj = 0; jj < 4; jj++) o[i][jj] = 0.f;
    }

    for (int j = 0; j <= qt; j++) {
        __syncthreads();
        const float* kbase = qkv + (size_t)(b * 1024 + j * 64) * 3072 + 1024 + h * 64;
#pragma unroll
        for (int it = 0; it < 4; it++) {
            int idx = it * 1024 + tid * 4;
            int kk = idx >> 6, d = idx & 63;
            float4 kv = *reinterpret_cast<const float4*>(kbase + (size_t)kk * 3072 + d);
            float4 vv = *reinterpret_cast<const float4*>(kbase + (size_t)kk * 3072 + 1024 + d);
            float* kp = Ks + kk * AT_PAD + d;
            float* vp = Vs + kk * AT_PAD + d;
            kp[0] = kv.x; kp[1] = kv.y; kp[2] = kv.z; kp[3] = kv.w;
            vp[0] = vv.x; vp[1] = vv.y; vp[2] = vv.z; vp[3] = vv.w;
        }
        __syncthreads();

        float s[4][4];
#pragma unroll
        for (int i = 0; i < 4; i++)
#pragma unroll
            for (int jj = 0; jj < 4; jj++) s[i][jj] = 0.f;
        const float* q0 = Qs + (qrow0 + 0) * AT_PAD;
        const float* q1 = Qs + (qrow0 + 1) * AT_PAD;
        const float* q2 = Qs + (qrow0 + 2) * AT_PAD;
        const float* q3 = Qs + (qrow0 + 3) * AT_PAD;
        const float* k0 = Ks + (kcol0 + 0) * AT_PAD;
        const float* k1 = Ks + (kcol0 + 1) * AT_PAD;
        const float* k2 = Ks + (kcol0 + 2) * AT_PAD;
        const float* k3 = Ks + (kcol0 + 3) * AT_PAD;
#pragma unroll 8
        for (int d = 0; d < 64; d++) {
            float qv0 = q0[d], qv1 = q1[d], qv2 = q2[d], qv3 = q3[d];
            float kv0 = k0[d], kv1 = k1[d], kv2 = k2[d], kv3 = k3[d];
            s[0][0] += qv0 * kv0; s[0][1] += qv0 * kv1; s[0][2] += qv0 * kv2; s[0][3] += qv0 * kv3;
            s[1][0] += qv1 * kv0; s[1][1] += qv1 * kv1; s[1][2] += qv1 * kv2; s[1][3] += qv1 * kv3;
            s[2][0] += qv2 * kv0; s[2][1] += qv2 * kv1; s[2][2] += qv2 * kv2; s[2][3] += qv2 * kv3;
            s[3][0] += qv3 * kv0; s[3][1] += qv3 * kv1; s[3][2] += qv3 * kv2; s[3][3] += qv3 * kv3;
        }
        if (j == qt) {
#pragma unroll
            for (int i = 0; i < 4; i++)
#pragma unroll
                for (int jj = 0; jj < 4; jj++)
                    if (kcol0 + jj > qrow0 + i) s[i][jj] = NEG_INF;
        }

#pragma unroll
        for (int i = 0; i < 4; i++) {
            float rm = fmaxf(fmaxf(s[i][0], s[i][1]), fmaxf(s[i][2], s[i][3]));
#pragma unroll
            for (int off = 8; off; off >>= 1)
                rm = fmaxf(rm, __shfl_xor_sync(0xffffffffu, rm, off, 16));
            float mn = fmaxf(m[i], rm);
            float sc = __expf(m[i] - mn);
            float rs = 0.f;
#pragma unroll
            for (int jj = 0; jj < 4; jj++) {
                float p = __expf(s[i][jj] - mn);
                s[i][jj] = p; rs += p;
            }
#pragma unroll
            for (int off = 8; off; off >>= 1)
                rs += __shfl_xor_sync(0xffffffffu, rs, off, 16);
            l[i] = l[i] * sc + rs;
            o[i][0] *= sc; o[i][1] *= sc; o[i][2] *= sc; o[i][3] *= sc;
            m[i] = mn;
            float* pp = Ps + (qrow0 + i) * AT_PAD + kcol0;
            pp[0] = s[i][0]; pp[1] = s[i][1]; pp[2] = s[i][2]; pp[3] = s[i][3];
        }
        __syncthreads();

        const float* P0 = Ps + (qrow0 + 0) * AT_PAD;
        const float* P1 = Ps + (qrow0 + 1) * AT_PAD;
        const float* P2 = Ps + (qrow0 + 2) * AT_PAD;
        const float* P3 = Ps + (qrow0 + 3) * AT_PAD;
#pragma unroll 8
        for (int kk = 0; kk < 64; kk++) {
            float p0 = P0[kk], p1 = P1[kk], p2 = P2[kk], p3 = P3[kk];
            const float* vr = Vs + kk * AT_PAD + kcol0;
            float v0 = vr[0], v1 = vr[1], v2 = vr[2], v3 = vr[3];
            o[0][0] += p0 * v0; o[0][1] += p0 * v1; o[0][2] += p0 * v2; o[0][3] += p0 * v3;
            o[1][0] += p1 * v0; o[1][1] += p1 * v1; o[1][2] += p1 * v2; o[1][3] += p1 * v3;
            o[2][0] += p2 * v0; o[2][1] += p2 * v1; o[2][2] += p2 * v2; o[2][3] += p2 * v3;
            o[3][0] += p3 * v0; o[3][1] += p3 * v1; o[3][2] += p3 * v2; o[3][3] += p3 * v3;
        }
    }

#pragma unroll
    for (int i = 0; i < 4; i++) {
        float inv = 1.0f / l[i];
        size_t base = (size_t)(b * 1024 + qt * 64 + qrow0 + i) * 1024 + h * 64 + kcol0;
#pragma unroll
        for (int jj = 0; jj < 4; jj++) {
            float gg = o[i][jj] * inv;
            __nv_bfloat16 hh, ll;
            bsplit(gg, hh, ll);
            yh[base + jj] = hh;
            yl[base + jj] = ll;
        }
    }
}

// ---------------------------------------------------------------------------
// Launch pipeline
// ---------------------------------------------------------------------------
extern "C" void kernel_launch(void* const* d_in, const int* in_sizes, int n_in,
                              void* d_out, int out_size) {
    const float* x      = (const float*)d_in[0];
    const float* ln1_w  = (const float*)d_in[1];
    const float* ln1_b  = (const float*)d_in[2];
    const float* w_qkv  = (const float*)d_in[3];
    const float* b_qkv  = (const float*)d_in[4];
    const float* w_o    = (const float*)d_in[5];
    const float* b_o    = (const float*)d_in[6];
    const float* ln2_w  = (const float*)d_in[7];
    const float* ln2_b  = (const float*)d_in[8];
    const float* w_fc   = (const float*)d_in[9];
    const float* b_fc   = (const float*)d_in[10];
    const float* w_proj = (const float*)d_in[11];
    const float* b_proj = (const float*)d_in[12];
    float* out = (float*)d_out;

    __nv_bfloat16 *p_lnh, *p_lnl, *p_atth, *p_attl, *p_hh, *p_hl;
    __nv_bfloat16 *p_wqkvh, *p_wqkvl, *p_woh, *p_wol, *p_wfch, *p_wfcl, *p_wprojh, *p_wprojl;
    float *p_qkv, *p_x1;
    cudaGetSymbolAddress((void**)&p_lnh,    g_lnh);
    cudaGetSymbolAddress((void**)&p_lnl,    g_lnl);
    cudaGetSymbolAddress((void**)&p_qkv,    g_qkv);
    cudaGetSymbolAddress((void**)&p_atth,   g_atth);
    cudaGetSymbolAddress((void**)&p_attl,   g_attl);
    cudaGetSymbolAddress((void**)&p_x1,     g_x1);
    cudaGetSymbolAddress((void**)&p_hh,     g_hh);
    cudaGetSymbolAddress((void**)&p_hl,     g_hl);
    cudaGetSymbolAddress((void**)&p_wqkvh,  g_wqkvh);
    cudaGetSymbolAddress((void**)&p_wqkvl,  g_wqkvl);
    cudaGetSymbolAddress((void**)&p_woh,    g_woh);
    cudaGetSymbolAddress((void**)&p_wol,    g_wol);
    cudaGetSymbolAddress((void**)&p_wfch,   g_wfch);
    cudaGetSymbolAddress((void**)&p_wfcl,   g_wfcl);
    cudaGetSymbolAddress((void**)&p_wprojh, g_wprojh);
    cudaGetSymbolAddress((void**)&p_wprojl, g_wprojl);

    cudaFuncSetAttribute(attn_kernel,
                         cudaFuncAttributeMaxDynamicSharedMemorySize, ATT_SMEM);
    cudaFuncSetAttribute(gemm_mma<0>,
                         cudaFuncAttributeMaxDynamicSharedMemorySize, GSMEM);
    cudaFuncSetAttribute(gemm_mma<1>,
                         cudaFuncAttributeMaxDynamicSharedMemorySize, GSMEM);
    cudaFuncSetAttribute(gemm_mma<2>,
                         cudaFuncAttributeMaxDynamicSharedMemorySize, GSMEM);

    dim3 tb(32, 8);
    // Weight transpose+split (cheap vs GEMMs)
    wsplit_kernel<<<dim3(3 * CDIM / 32, CDIM / 32), tb>>>(w_qkv, p_wqkvh, p_wqkvl, CDIM, 3 * CDIM);
    wsplit_kernel<<<dim3(CDIM / 32, CDIM / 32), tb>>>(w_o, p_woh, p_wol, CDIM, CDIM);
    wsplit_kernel<<<dim3(4 * CDIM / 32, CDIM / 32), tb>>>(w_fc, p_wfch, p_wfcl, CDIM, 4 * CDIM);
    wsplit_kernel<<<dim3(CDIM / 32, 4 * CDIM / 32), tb>>>(w_proj, p_wprojh, p_wprojl, 4 * CDIM, CDIM);

    // 1) LN1 -> bf16 hi/lo
    ln_split_kernel<<<BT, 256>>>(x, ln1_w, ln1_b, p_lnh, p_lnl);
    // 2) qkv = ln1 @ w_qkv + b_qkv  (f32 out)   [8192,3072]
    gemm_mma<0><<<dim3(24, 64), 256, GSMEM>>>(p_lnh, p_lnl, p_wqkvh, p_wqkvl,
                                              b_qkv, nullptr, p_qkv, nullptr, nullptr,
                                              BT, 3 * CDIM, CDIM);
    // 3) attention -> bf16 hi/lo                [8192,1024]
    attn_kernel<<<dim3(16, 16, 8), 256, ATT_SMEM>>>(p_qkv, p_atth, p_attl);
    // 4) x1 = att @ w_o + b_o + x  (f32 out)
    gemm_mma<1><<<dim3(8, 64), 256, GSMEM>>>(p_atth, p_attl, p_woh, p_wol,
                                             b_o, x, p_x1, nullptr, nullptr,
                                             BT, CDIM, CDIM);
    // 5) LN2 -> bf16 hi/lo
    ln_split_kernel<<<BT, 256>>>(p_x1, ln2_w, ln2_b, p_lnh, p_lnl);
    // 6) h = gelu(ln2 @ w_fc + b_fc) -> bf16 hi/lo   [8192,4096]
    gemm_mma<2><<<dim3(32, 64), 256, GSMEM>>>(p_lnh, p_lnl, p_wfch, p_wfcl,
                                              b_fc, nullptr, nullptr, p_hh, p_hl,
                                              BT, 4 * CDIM, CDIM);
    // 7) out = h @ w_proj + b_proj + x1  (f32 out)
    gemm_mma<1><<<dim3(8, 64), 256, GSMEM>>>(p_hh, p_hl, p_wprojh, p_wprojl,
                                             b_proj, p_x1, out, nullptr, nullptr,
                                             BT, CDIM, 4 * CDIM);
}